// round 1
// baseline (speedup 1.0000x reference)
#include <cuda_runtime.h>
#include <math.h>

#define C_DIM 768
#define NSEQ  4096
#define HEADS 12
#define HD    64

// scratch (allocation-free rule: __device__ globals)
__device__ float g_qkv[(size_t)NSEQ * 3 * C_DIM];   // [N, 3C] : q|k|v per row
__device__ float g_att[(size_t)NSEQ * C_DIM];       // [N, C]  : attention output

// ---------------------------------------------------------------------------
// SGEMM NT: C[M][N] = A[M][K] @ B[N][K]^T + bias[N]
// BM=BN=128, BK=8, 256 threads, 8x8 microtile per thread.
// All problem dims are multiples of the tiles -> no edge handling.
// ---------------------------------------------------------------------------
template<int BM, int BN, int BK, int TM, int TN>
__global__ __launch_bounds__(256)
void sgemm_nt(const float* __restrict__ A, const float* __restrict__ B,
              const float* __restrict__ bias, float* __restrict__ C,
              int M, int N, int K)
{
    __shared__ float As[BK][BM];
    __shared__ float Bs[BK][BN];

    const int tid = threadIdx.x;
    const int tx = tid & 15;        // 0..15
    const int ty = tid >> 4;        // 0..15
    const int m0 = blockIdx.y * BM;
    const int n0 = blockIdx.x * BN;

    float acc[TM][TN] = {};

    for (int k0 = 0; k0 < K; k0 += BK) {
        // load A tile (BM x BK) transposed into As[BK][BM]
        #pragma unroll
        for (int i = 0; i < (BM * BK) / 256; i++) {
            int e = tid + i * 256;
            int r = e / BK, c = e % BK;
            As[c][r] = A[(size_t)(m0 + r) * K + k0 + c];
        }
        // load B tile (BN x BK) transposed into Bs[BK][BN]
        #pragma unroll
        for (int i = 0; i < (BN * BK) / 256; i++) {
            int e = tid + i * 256;
            int r = e / BK, c = e % BK;
            Bs[c][r] = B[(size_t)(n0 + r) * K + k0 + c];
        }
        __syncthreads();

        #pragma unroll
        for (int kk = 0; kk < BK; kk++) {
            float a[TM], b[TN];
            #pragma unroll
            for (int i = 0; i < TM; i++) a[i] = As[kk][ty * TM + i];
            #pragma unroll
            for (int j = 0; j < TN; j++) b[j] = Bs[kk][tx * TN + j];
            #pragma unroll
            for (int i = 0; i < TM; i++)
                #pragma unroll
                for (int j = 0; j < TN; j++)
                    acc[i][j] += a[i] * b[j];
        }
        __syncthreads();
    }

    #pragma unroll
    for (int i = 0; i < TM; i++) {
        int row = m0 + ty * TM + i;
        #pragma unroll
        for (int j = 0; j < TN; j++) {
            int col = n0 + tx * TN + j;
            C[(size_t)row * N + col] = acc[i][j] + bias[col];
        }
    }
}

// ---------------------------------------------------------------------------
// Flash attention, fp32. One thread owns one query row (128 rows / block).
// Key/value tiles of 32 rows staged in shared; scores staged in padded shared
// to keep registers at q[64] + o[64].
// q is pre-scaled by 8 (reference quirk: q / D^-0.5 = q * sqrt(64)).
// ---------------------------------------------------------------------------
#define FBM 128
#define FBN 32

__global__ __launch_bounds__(128)
void flash_kernel(const float* __restrict__ qkv, float* __restrict__ attn_out)
{
    __shared__ float4 Ks[FBN][HD / 4];          // 8 KB
    __shared__ float4 Vs[FBN][HD / 4];          // 8 KB
    __shared__ float  Ps[FBM][FBN + 1];         // ~16.9 KB, padded vs bank conflicts

    const int tid  = threadIdx.x;
    const int h    = blockIdx.y;
    const int qrow = blockIdx.x * FBM + tid;

    // q row into registers, scaled by 8
    const float* qptr = qkv + (size_t)qrow * (3 * C_DIM) + h * HD;
    float4 q[HD / 4];
    #pragma unroll
    for (int i = 0; i < HD / 4; i++) {
        float4 t = reinterpret_cast<const float4*>(qptr)[i];
        t.x *= 8.f; t.y *= 8.f; t.z *= 8.f; t.w *= 8.f;
        q[i] = t;
    }

    float o[HD] = {};
    float mrun = -INFINITY, lrun = 0.f;

    for (int kt = 0; kt < NSEQ / FBN; kt++) {
        // cooperative load of K and V tiles (FBN x HD each), float4, coalesced per row
        #pragma unroll
        for (int i = 0; i < (FBN * HD / 4) / 128; i++) {
            int e = tid + i * 128;
            int r = e / (HD / 4), c = e % (HD / 4);
            size_t base = (size_t)(kt * FBN + r) * (3 * C_DIM) + h * HD + c * 4;
            Ks[r][c] = *reinterpret_cast<const float4*>(qkv + base + C_DIM);
            Vs[r][c] = *reinterpret_cast<const float4*>(qkv + base + 2 * C_DIM);
        }
        __syncthreads();

        // scores for this thread's row
        float tmax = -INFINITY;
        #pragma unroll
        for (int j = 0; j < FBN; j++) {
            float s = 0.f;
            #pragma unroll
            for (int c = 0; c < HD / 4; c++) {
                float4 k4 = Ks[j][c];
                s += q[c].x * k4.x + q[c].y * k4.y + q[c].z * k4.z + q[c].w * k4.w;
            }
            Ps[tid][j] = s;
            tmax = fmaxf(tmax, s);
        }

        float mnew = fmaxf(mrun, tmax);
        float corr = __expf(mrun - mnew);      // first tile: exp(-inf) = 0
        lrun *= corr;
        #pragma unroll
        for (int d = 0; d < HD; d++) o[d] *= corr;

        #pragma unroll
        for (int j = 0; j < FBN; j++) {
            float p = __expf(Ps[tid][j] - mnew);
            Ps[tid][j] = p;
            lrun += p;
        }

        // O += P @ V
        #pragma unroll
        for (int j = 0; j < FBN; j++) {
            float p = Ps[tid][j];
            #pragma unroll
            for (int c = 0; c < HD / 4; c++) {
                float4 v4 = Vs[j][c];
                o[c * 4 + 0] += p * v4.x;
                o[c * 4 + 1] += p * v4.y;
                o[c * 4 + 2] += p * v4.z;
                o[c * 4 + 3] += p * v4.w;
            }
        }
        mrun = mnew;
        __syncthreads();
    }

    const float inv = 1.f / lrun;
    float* op = attn_out + (size_t)qrow * C_DIM + h * HD;
    #pragma unroll
    for (int d = 0; d < HD; d++) op[d] = o[d] * inv;
}

// ---------------------------------------------------------------------------
extern "C" void kernel_launch(void* const* d_in, const int* in_sizes, int n_in,
                              void* d_out, int out_size)
{
    (void)in_sizes; (void)n_in; (void)out_size;
    const float* x      = (const float*)d_in[0];
    const float* qkv_w  = (const float*)d_in[1];
    const float* qkv_b  = (const float*)d_in[2];
    const float* proj_w = (const float*)d_in[3];
    const float* proj_b = (const float*)d_in[4];
    float* out = (float*)d_out;

    float *qkv_p = nullptr, *att_p = nullptr;
    cudaGetSymbolAddress((void**)&qkv_p, g_qkv);
    cudaGetSymbolAddress((void**)&att_p, g_att);

    // 1) QKV projection: [4096,768] @ [2304,768]^T -> [4096,2304]
    dim3 g1((3 * C_DIM) / 128, NSEQ / 128);
    sgemm_nt<128, 128, 8, 8, 8><<<g1, 256>>>(x, qkv_w, qkv_b, qkv_p,
                                             NSEQ, 3 * C_DIM, C_DIM);

    // 2) Flash attention per head -> [4096,768] (already in [N, H*D] layout)
    dim3 g2(NSEQ / FBM, HEADS);
    flash_kernel<<<g2, 128>>>(qkv_p, att_p);

    // 3) Output projection: [4096,768] @ [768,768]^T -> d_out
    dim3 g3(C_DIM / 128, NSEQ / 128);
    sgemm_nt<128, 128, 8, 8, 8><<<g3, 256>>>(att_p, proj_w, proj_b, out,
                                             NSEQ, C_DIM, C_DIM);
}